// round 3
// baseline (speedup 1.0000x reference)
#include <cuda_runtime.h>
#include <cuda_bf16.h>

#define N_NODES  100000
#define N_EDGES  3200000
#define IN_DIM   128
#define H1       32
#define H2       16
#define N_GRAPHS 512

// ---------------- scratch (static __device__ arrays — no allocation) ----------------
__device__ __align__(128) int   d_deg[N_NODES];
__device__ __align__(128) int   d_rowptr[N_NODES + 1];
__device__ __align__(128) int   d_cursor[N_NODES];
__device__ __align__(128) int   d_col[N_EDGES];
__device__ __align__(128) float d_dinv[N_NODES];
__device__ __align__(128) float d_g1[(size_t)N_NODES * H1];
__device__ __align__(128) float d_g2[(size_t)N_NODES * H2];
__device__ __align__(128) float d_pool[N_GRAPHS * H2];
__device__ __align__(128) float d_cnt[N_GRAPHS];

// ---------------- 1. zero per-launch accumulators ----------------
__global__ void k_zero() {
    int i = blockIdx.x * blockDim.x + threadIdx.x;
    if (i < N_NODES) d_deg[i] = 0;
    if (i < N_GRAPHS * H2) d_pool[i] = 0.f;
    if (i < N_GRAPHS) d_cnt[i] = 0.f;
}

// ---------------- 2. degree histogram over dst (edge_index is int32!) ----------------
__global__ void k_deg(const int* __restrict__ ei) {
    int i = blockIdx.x * blockDim.x + threadIdx.x;
    if (i < N_EDGES) {
        int dst = ei[N_EDGES + i];
        if ((unsigned)dst < N_NODES) atomicAdd(&d_deg[dst], 1);
    }
}

// ---------------- 3. single-block exclusive scan + dinv ----------------
__global__ void k_scan() {
    const int T = 1024;
    __shared__ int sums[T];
    int t = threadIdx.x;
    const int chunk = (N_NODES + T - 1) / T;  // 98
    int lo = t * chunk;
    int hi = lo + chunk; if (hi > N_NODES) hi = N_NODES;
    if (lo > N_NODES) lo = N_NODES;
    int local = 0;
    for (int i = lo; i < hi; i++) local += d_deg[i];
    sums[t] = local;
    __syncthreads();
    // Hillis-Steele inclusive scan
    for (int off = 1; off < T; off <<= 1) {
        int v = (t >= off) ? sums[t - off] : 0;
        __syncthreads();
        sums[t] += v;
        __syncthreads();
    }
    int run = sums[t] - local;  // exclusive prefix of this thread's chunk
    for (int i = lo; i < hi; i++) {
        d_rowptr[i] = run;
        d_cursor[i] = run;
        int dg = d_deg[i];
        run += dg;
        d_dinv[i] = rsqrtf((float)(dg + 1));  // +1 self-loop, always >= 1
    }
    if (t == T - 1) d_rowptr[N_NODES] = sums[T - 1];
}

// ---------------- 4. CSR fill (scatter src by dst) ----------------
__global__ void k_csr(const int* __restrict__ ei) {
    int i = blockIdx.x * blockDim.x + threadIdx.x;
    if (i < N_EDGES) {
        int s = ei[i];
        int d = ei[N_EDGES + i];
        if ((unsigned)d < N_NODES && (unsigned)s < N_NODES) {
            int p = atomicAdd(&d_cursor[d], 1);
            d_col[p] = s;
        }
    }
}

// ---------------- 5. g1 = dinv * (x @ W1) ----------------
// block = 256 threads = 8 warps; warp w handles node blockIdx*8+w; lane = output col
__global__ void k_gemm1(const float* __restrict__ x, const float* __restrict__ W1) {
    __shared__ float W1s[IN_DIM * H1];   // 16 KB
    __shared__ float xs[8][IN_DIM];      // 4 KB
    int tid = threadIdx.x;
    for (int i = tid; i < IN_DIM * H1; i += 256) W1s[i] = W1[i];
    __syncthreads();
    int wid = tid >> 5, lane = tid & 31;
    int node = blockIdx.x * 8 + wid;
    if (node >= N_NODES) return;
    // cooperative row load: 32 lanes x float4 = 128 floats
    const float4* xr = (const float4*)(x + (size_t)node * IN_DIM);
    ((float4*)xs[wid])[lane] = xr[lane];
    __syncwarp();
    float acc = 0.f;
#pragma unroll
    for (int k = 0; k < IN_DIM; k++)
        acc = fmaf(xs[wid][k], W1s[k * H1 + lane], acc);
    d_g1[(size_t)node * H1 + lane] = d_dinv[node] * acc;
}

// ---------------- 6. layer-1 aggregate + ReLU + (h1 @ W2) fused ----------------
// warp per node, lane = feature (32 features). Epilogue computes g2 = dinv*(h1@W2).
__global__ void k_agg1(const float* __restrict__ b1, const float* __restrict__ W2) {
    __shared__ float W2s[H1 * H2];  // 2 KB
    int tid = threadIdx.x;
    for (int i = tid; i < H1 * H2; i += 256) W2s[i] = W2[i];
    __syncthreads();
    int wid = tid >> 5, lane = tid & 31;
    int node = blockIdx.x * 8 + wid;
    if (node >= N_NODES) return;

    float acc = d_g1[(size_t)node * H1 + lane];  // self-loop term
    int s = d_rowptr[node], e = d_rowptr[node + 1];
    int i = s;
    for (; i + 4 <= e; i += 4) {                 // unroll 4 for MLP
        int c0 = d_col[i], c1 = d_col[i + 1], c2 = d_col[i + 2], c3 = d_col[i + 3];
        float a0 = d_g1[(size_t)c0 * H1 + lane];
        float a1 = d_g1[(size_t)c1 * H1 + lane];
        float a2 = d_g1[(size_t)c2 * H1 + lane];
        float a3 = d_g1[(size_t)c3 * H1 + lane];
        acc += (a0 + a1) + (a2 + a3);
    }
    for (; i < e; ++i) acc += d_g1[(size_t)d_col[i] * H1 + lane];

    float di = d_dinv[node];
    float h = fmaxf(di * acc + b1[lane], 0.f);  // h1[node][lane]

    // g2[node][j] = di * sum_c h1[c] * W2[c][j], j < 16, via warp shuffle broadcast
    float o = 0.f;
    int f = lane & 15;
#pragma unroll
    for (int c = 0; c < H1; c++) {
        float v = __shfl_sync(0xffffffffu, h, c);
        o = fmaf(v, W2s[c * H2 + f], o);
    }
    if (lane < H2) d_g2[(size_t)node * H2 + lane] = di * o;
}

// ---------------- 7. layer-2 aggregate + ReLU + mean-pool scatter fused ----------------
// warp per node; two half-warps process two neighbors per iteration (16 features).
__global__ void k_agg2(const float* __restrict__ b2, const int* __restrict__ batch) {
    int tid = threadIdx.x;
    int wid = tid >> 5, lane = tid & 31;
    int node = blockIdx.x * 8 + wid;
    if (node >= N_NODES) return;

    int half = lane >> 4, f = lane & 15;
    float acc = (half == 0) ? d_g2[(size_t)node * H2 + f] : 0.f;  // self-loop once
    int s = d_rowptr[node], e = d_rowptr[node + 1];
    int i = s + half;
    for (; i + 2 < e; i += 4) {   // each half handles neighbors i and i+2
        float a0 = d_g2[(size_t)d_col[i] * H2 + f];
        float a1 = d_g2[(size_t)d_col[i + 2] * H2 + f];
        acc += a0 + a1;
    }
    for (; i < e; i += 2) acc += d_g2[(size_t)d_col[i] * H2 + f];
    acc += __shfl_xor_sync(0xffffffffu, acc, 16);  // combine half-warps

    float di = d_dinv[node];
    float h = fmaxf(di * acc + b2[f], 0.f);  // h2[node][f]

    int g = batch[node];
    if ((unsigned)g < N_GRAPHS) {
        if (half == 0) atomicAdd(&d_pool[g * H2 + f], h);
        if (lane == 0) atomicAdd(&d_cnt[g], 1.f);
    }
}

// ---------------- 8. output head: (pool_sum / count) @ W3 + b3 ----------------
__global__ void k_out(const float* __restrict__ W3, const float* __restrict__ b3,
                      float* __restrict__ out) {
    int g = blockIdx.x * blockDim.x + threadIdx.x;
    if (g < N_GRAPHS) {
        float c = fmaxf(d_cnt[g], 1.f);
        float sm = 0.f;
#pragma unroll
        for (int j = 0; j < H2; j++) sm = fmaf(d_pool[g * H2 + j], W3[j], sm);
        out[g] = sm / c + b3[0];
    }
}

// ---------------- launch ----------------
extern "C" void kernel_launch(void* const* d_in, const int* in_sizes, int n_in,
                              void* d_out, int out_size) {
    const float* x     = (const float*)d_in[0];
    const int*   ei    = (const int*)d_in[1];     // int64 canonicalized to int32
    const int*   batch = (const int*)d_in[2];     // int64 canonicalized to int32
    const float* W1    = (const float*)d_in[3];
    const float* b1    = (const float*)d_in[4];
    const float* W2    = (const float*)d_in[5];
    const float* b2    = (const float*)d_in[6];
    const float* W3    = (const float*)d_in[7];
    const float* b3    = (const float*)d_in[8];
    float* out = (float*)d_out;

    const int ZB = (N_NODES + 255) / 256;        // 391
    const int EB = (N_EDGES + 255) / 256;        // 12500
    const int NB = (N_NODES + 7) / 8;            // 12500 (warp-per-node kernels)

    k_zero<<<ZB, 256>>>();
    k_deg<<<EB, 256>>>(ei);
    k_scan<<<1, 1024>>>();
    k_csr<<<EB, 256>>>(ei);
    k_gemm1<<<NB, 256>>>(x, W1);
    k_agg1<<<NB, 256>>>(b1, W2);
    k_agg2<<<NB, 256>>>(b2, batch);
    k_out<<<(N_GRAPHS + 255) / 256, 256>>>(W3, b3, out);
}

// round 4
// speedup vs baseline: 1.6484x; 1.6484x over previous
#include <cuda_runtime.h>
#include <cuda_bf16.h>

#define N_NODES  100000
#define N_EDGES  3200000
#define IN_DIM   128
#define H1       32
#define H2       16
#define N_GRAPHS 512

#define GEMM_TM      64
#define GEMM_BLOCKS  ((N_NODES + GEMM_TM - 1) / GEMM_TM)      // 1563
#define E4           (N_EDGES / 4)                             // 800000
#define EDGE_BLOCKS  ((E4 + 255) / 256)                        // 3125
#define SCAN_BLOCKS  ((N_NODES + 255) / 256)                   // 391
#define SCALE_VEC    (N_NODES * H1 / 4)                        // 800000
#define SCALE_BLOCKS ((SCALE_VEC + 255) / 256)                 // 3125

// ---------------- scratch (static __device__ arrays — no allocation) ----------------
__device__ __align__(128) int   d_deg[N_NODES];
__device__ __align__(128) int   d_rowptr[N_NODES + 1];
__device__ __align__(128) int   d_cursor[N_NODES];
__device__ __align__(128) int   d_col[N_EDGES];
__device__ __align__(128) float d_dinv[N_NODES];
__device__ __align__(128) int   d_bsum[512];
__device__ __align__(128) int   d_boff[512];
__device__ __align__(128) float d_g1[(size_t)N_NODES * H1];
__device__ __align__(128) float d_g2[(size_t)N_NODES * H2];
__device__ __align__(128) float d_pool[N_GRAPHS * H2];

// ---------------- 1. zero accumulators ----------------
__global__ void k_zero() {
    int i = blockIdx.x * blockDim.x + threadIdx.x;
    if (i < N_NODES) d_deg[i] = 0;
    if (i < N_GRAPHS * H2) d_pool[i] = 0.f;
}

// ---------------- 2. fused: raw GEMM (y1 = x @ W1) || degree histogram ----------------
// GEMM: block = 256 thr computes 64 nodes x 32 cols. Thread = 2 nodes x 4 cols.
// x tile in smem (padded stride 132, conflict-free); W1 rows via LDG (L1-resident 16KB).
// DEG: 4 edges/thread via int4, 4 independent atomics (MLP=4).
__global__ void __launch_bounds__(256) k_gemm_deg(const float* __restrict__ x,
                                                  const float* __restrict__ W1,
                                                  const int* __restrict__ ei) {
    if (blockIdx.x >= GEMM_BLOCKS) {
        int i = (blockIdx.x - GEMM_BLOCKS) * 256 + threadIdx.x;
        if (i < E4) {
            int4 dd = ((const int4*)(ei + N_EDGES))[i];
            if ((unsigned)dd.x < N_NODES) atomicAdd(&d_deg[dd.x], 1);
            if ((unsigned)dd.y < N_NODES) atomicAdd(&d_deg[dd.y], 1);
            if ((unsigned)dd.z < N_NODES) atomicAdd(&d_deg[dd.z], 1);
            if ((unsigned)dd.w < N_NODES) atomicAdd(&d_deg[dd.w], 1);
        }
        return;
    }
    __shared__ float xs[GEMM_TM * 132];   // 33.8 KB, padded rows
    int tid = threadIdx.x;
    int n0 = blockIdx.x * GEMM_TM;
    // cooperative x-tile load (float4, coalesced), zero-fill past N_NODES
    for (int i = tid; i < GEMM_TM * (IN_DIM / 4); i += 256) {
        int r = i >> 5, c = i & 31;
        float4 v = make_float4(0.f, 0.f, 0.f, 0.f);
        if (n0 + r < N_NODES)
            v = ((const float4*)(x + (size_t)(n0 + r) * IN_DIM))[c];
        *((float4*)(xs + r * 132 + c * 4)) = v;
    }
    __syncthreads();
    int tx = tid & 7;     // 8 col groups of 4
    int ty = tid >> 3;    // 32 node groups of 2
    const float* xr0 = xs + (2 * ty) * 132;
    const float* xr1 = xs + (2 * ty + 1) * 132;
    float a00 = 0.f, a01 = 0.f, a02 = 0.f, a03 = 0.f;
    float a10 = 0.f, a11 = 0.f, a12 = 0.f, a13 = 0.f;
    const float4* Wv = (const float4*)(W1) + tx;   // W1[k*32 + 4tx]
#pragma unroll 8
    for (int k = 0; k < IN_DIM; k++) {
        float4 w = __ldg(Wv + k * 8);
        float p0 = xr0[k], p1 = xr1[k];
        a00 = fmaf(p0, w.x, a00); a01 = fmaf(p0, w.y, a01);
        a02 = fmaf(p0, w.z, a02); a03 = fmaf(p0, w.w, a03);
        a10 = fmaf(p1, w.x, a10); a11 = fmaf(p1, w.y, a11);
        a12 = fmaf(p1, w.z, a12); a13 = fmaf(p1, w.w, a13);
    }
    int n = n0 + 2 * ty;
    if (n < N_NODES)
        *((float4*)(d_g1 + (size_t)n * H1 + 4 * tx)) = make_float4(a00, a01, a02, a03);
    if (n + 1 < N_NODES)
        *((float4*)(d_g1 + (size_t)(n + 1) * H1 + 4 * tx)) = make_float4(a10, a11, a12, a13);
}

// ---------------- 3a. block-level scan of degrees ----------------
__global__ void __launch_bounds__(256) k_scan_a() {
    int t = threadIdx.x, b = blockIdx.x;
    int i = b * 256 + t;
    int v = (i < N_NODES) ? d_deg[i] : 0;
    int lane = t & 31, wid = t >> 5;
    int xsum = v;
#pragma unroll
    for (int off = 1; off < 32; off <<= 1) {
        int y = __shfl_up_sync(0xffffffffu, xsum, off);
        if (lane >= off) xsum += y;
    }
    __shared__ int wsum[8], woff[8];
    if (lane == 31) wsum[wid] = xsum;
    __syncthreads();
    if (t == 0) {
        int r = 0;
#pragma unroll
        for (int j = 0; j < 8; j++) { woff[j] = r; r += wsum[j]; }
        d_bsum[b] = r;
    }
    __syncthreads();
    int excl = xsum - v + woff[wid];
    if (i < N_NODES) d_rowptr[i] = excl;    // local prefix (temp)
}

// ---------------- 3b. scan of 391 block sums (1 block) ----------------
__global__ void __launch_bounds__(512) k_scan_b() {
    int t = threadIdx.x;
    int v = (t < SCAN_BLOCKS) ? d_bsum[t] : 0;
    int lane = t & 31, wid = t >> 5;
    int xsum = v;
#pragma unroll
    for (int off = 1; off < 32; off <<= 1) {
        int y = __shfl_up_sync(0xffffffffu, xsum, off);
        if (lane >= off) xsum += y;
    }
    __shared__ int wsum[16], woff[16];
    if (lane == 31) wsum[wid] = xsum;
    __syncthreads();
    if (t == 0) {
        int r = 0;
#pragma unroll
        for (int j = 0; j < 16; j++) { woff[j] = r; r += wsum[j]; }
        d_rowptr[N_NODES] = r;   // grand total = N_EDGES (valid edges)
    }
    __syncthreads();
    int excl = xsum - v + woff[wid];
    if (t < SCAN_BLOCKS) d_boff[t] = excl;
}

// ---------------- 3c. finalize rowptr/cursor/dinv ----------------
__global__ void __launch_bounds__(256) k_scan_c() {
    int i = blockIdx.x * 256 + threadIdx.x;
    if (i < N_NODES) {
        int r = d_rowptr[i] + d_boff[blockIdx.x];
        d_rowptr[i] = r;
        d_cursor[i] = r;
        d_dinv[i] = rsqrtf((float)(d_deg[i] + 1));
    }
}

// ---------------- 4. fused: CSR fill || g1 *= dinv ----------------
__global__ void __launch_bounds__(256) k_csr_scale(const int* __restrict__ ei) {
    if (blockIdx.x < EDGE_BLOCKS) {
        int i = blockIdx.x * 256 + threadIdx.x;
        if (i < E4) {
            int4 ss = ((const int4*)ei)[i];
            int4 dd = ((const int4*)(ei + N_EDGES))[i];
            if ((unsigned)dd.x < N_NODES && (unsigned)ss.x < N_NODES)
                d_col[atomicAdd(&d_cursor[dd.x], 1)] = ss.x;
            if ((unsigned)dd.y < N_NODES && (unsigned)ss.y < N_NODES)
                d_col[atomicAdd(&d_cursor[dd.y], 1)] = ss.y;
            if ((unsigned)dd.z < N_NODES && (unsigned)ss.z < N_NODES)
                d_col[atomicAdd(&d_cursor[dd.z], 1)] = ss.z;
            if ((unsigned)dd.w < N_NODES && (unsigned)ss.w < N_NODES)
                d_col[atomicAdd(&d_cursor[dd.w], 1)] = ss.w;
        }
    } else {
        int i = (blockIdx.x - EDGE_BLOCKS) * 256 + threadIdx.x;
        if (i < SCALE_VEC) {
            int node = i >> 3;                 // 8 float4 per node row
            float di = d_dinv[node];
            float4 v = ((float4*)d_g1)[i];
            v.x *= di; v.y *= di; v.z *= di; v.w *= di;
            ((float4*)d_g1)[i] = v;
        }
    }
}

// ---------------- 5. layer-1 aggregate + ReLU + (h1 @ W2) fused ----------------
// warp per node, lane = feature. g1 row = 128B = 1 L2 line per gather.
__global__ void __launch_bounds__(256) k_agg1(const float* __restrict__ b1,
                                              const float* __restrict__ W2) {
    __shared__ float W2s[H1 * H2];
    int tid = threadIdx.x;
    for (int i = tid; i < H1 * H2; i += 256) W2s[i] = W2[i];
    __syncthreads();
    int wid = tid >> 5, lane = tid & 31;
    int node = blockIdx.x * 8 + wid;
    if (node >= N_NODES) return;

    float acc0 = d_g1[(size_t)node * H1 + lane];  // self-loop term
    float acc1 = 0.f;
    int s = d_rowptr[node], e = d_rowptr[node + 1];
    int i = s;
    for (; i + 8 <= e; i += 8) {
        int c0 = d_col[i],     c1 = d_col[i + 1], c2 = d_col[i + 2], c3 = d_col[i + 3];
        int c4 = d_col[i + 4], c5 = d_col[i + 5], c6 = d_col[i + 6], c7 = d_col[i + 7];
        float v0 = d_g1[(size_t)c0 * H1 + lane];
        float v1 = d_g1[(size_t)c1 * H1 + lane];
        float v2 = d_g1[(size_t)c2 * H1 + lane];
        float v3 = d_g1[(size_t)c3 * H1 + lane];
        float v4 = d_g1[(size_t)c4 * H1 + lane];
        float v5 = d_g1[(size_t)c5 * H1 + lane];
        float v6 = d_g1[(size_t)c6 * H1 + lane];
        float v7 = d_g1[(size_t)c7 * H1 + lane];
        acc0 += (v0 + v1) + (v2 + v3);
        acc1 += (v4 + v5) + (v6 + v7);
    }
    for (; i < e; ++i) acc0 += d_g1[(size_t)d_col[i] * H1 + lane];
    float acc = acc0 + acc1;

    float di = d_dinv[node];
    float h = fmaxf(di * acc + b1[lane], 0.f);    // h1[node][lane]

    // g2[node][j] = di * sum_c h1[c] * W2[c][j] via warp shuffle broadcast
    float o = 0.f;
    int f = lane & 15;
#pragma unroll
    for (int c = 0; c < H1; c++) {
        float v = __shfl_sync(0xffffffffu, h, c);
        o = fmaf(v, W2s[c * H2 + f], o);
    }
    if (lane < H2) d_g2[(size_t)node * H2 + lane] = di * o;
}

// ---------------- 6. layer-2 aggregate + ReLU + mean-pool scatter fused ----------------
// warp per node; half-warps interleave neighbors (16 features each).
__global__ void __launch_bounds__(256) k_agg2(const float* __restrict__ b2,
                                              const int* __restrict__ batch) {
    int tid = threadIdx.x;
    int wid = tid >> 5, lane = tid & 31;
    int node = blockIdx.x * 8 + wid;
    if (node >= N_NODES) return;

    int half = lane >> 4, f = lane & 15;
    float acc = (half == 0) ? d_g2[(size_t)node * H2 + f] : 0.f;  // self-loop once
    int s = d_rowptr[node], e = d_rowptr[node + 1];
    int i = s + half;
    for (; i + 6 < e; i += 8) {   // each half handles 4 neighbors per iter
        float v0 = d_g2[(size_t)d_col[i]     * H2 + f];
        float v1 = d_g2[(size_t)d_col[i + 2] * H2 + f];
        float v2 = d_g2[(size_t)d_col[i + 4] * H2 + f];
        float v3 = d_g2[(size_t)d_col[i + 6] * H2 + f];
        acc += (v0 + v1) + (v2 + v3);
    }
    for (; i < e; i += 2) acc += d_g2[(size_t)d_col[i] * H2 + f];
    acc += __shfl_xor_sync(0xffffffffu, acc, 16);  // combine half-warps

    float di = d_dinv[node];
    float h = fmaxf(di * acc + b2[f], 0.f);        // h2[node][f]

    int g = batch[node];
    if ((unsigned)g < N_GRAPHS && half == 0)
        atomicAdd(&d_pool[g * H2 + f], h);
}

// ---------------- 7. output head: counts via binary search on sorted batch ----------------
__global__ void k_out(const int* __restrict__ batch, const float* __restrict__ W3,
                      const float* __restrict__ b3, float* __restrict__ out) {
    int g = blockIdx.x * blockDim.x + threadIdx.x;
    if (g >= N_GRAPHS) return;
    // lower_bound(g) and lower_bound(g+1) on sorted batch
    int lo0 = 0, hi0 = N_NODES;
    while (lo0 < hi0) { int m = (lo0 + hi0) >> 1; if (batch[m] < g) lo0 = m + 1; else hi0 = m; }
    int lo1 = lo0, hi1 = N_NODES;
    while (lo1 < hi1) { int m = (lo1 + hi1) >> 1; if (batch[m] < g + 1) lo1 = m + 1; else hi1 = m; }
    float c = fmaxf((float)(lo1 - lo0), 1.f);
    float sm = 0.f;
#pragma unroll
    for (int j = 0; j < H2; j++) sm = fmaf(d_pool[g * H2 + j], W3[j], sm);
    out[g] = sm / c + b3[0];
}

// ---------------- launch ----------------
extern "C" void kernel_launch(void* const* d_in, const int* in_sizes, int n_in,
                              void* d_out, int out_size) {
    const float* x     = (const float*)d_in[0];
    const int*   ei    = (const int*)d_in[1];     // int64 canonicalized to int32
    const int*   batch = (const int*)d_in[2];
    const float* W1    = (const float*)d_in[3];
    const float* b1    = (const float*)d_in[4];
    const float* W2    = (const float*)d_in[5];
    const float* b2    = (const float*)d_in[6];
    const float* W3    = (const float*)d_in[7];
    const float* b3    = (const float*)d_in[8];
    float* out = (float*)d_out;

    const int NB = (N_NODES + 7) / 8;   // warp-per-node kernels: 12500

    k_zero<<<SCAN_BLOCKS, 256>>>();
    k_gemm_deg<<<GEMM_BLOCKS + EDGE_BLOCKS, 256>>>(x, W1, ei);
    k_scan_a<<<SCAN_BLOCKS, 256>>>();
    k_scan_b<<<1, 512>>>();
    k_scan_c<<<SCAN_BLOCKS, 256>>>();
    k_csr_scale<<<EDGE_BLOCKS + SCALE_BLOCKS, 256>>>(ei);
    k_agg1<<<NB, 256>>>(b1, W2);
    k_agg2<<<NB, 256>>>(b2, batch);
    k_out<<<(N_GRAPHS + 255) / 256, 256>>>(batch, W3, b3, out);
}

// round 6
// speedup vs baseline: 2.2690x; 1.3765x over previous
#include <cuda_runtime.h>
#include <cuda_fp16.h>

#define N_NODES  100000
#define N_EDGES  3200000
#define IN_DIM   128
#define H1       32
#define H2       16
#define N_GRAPHS 512

#define GEMM_TM      64
#define GEMM_BLOCKS  ((N_NODES + GEMM_TM - 1) / GEMM_TM)      // 1563
#define E4           (N_EDGES / 4)                             // 800000
#define EDGE_BLOCKS  ((E4 + 255) / 256)                        // 3125
#define SCAN_BLOCKS  ((N_NODES + 255) / 256)                   // 391
#define SCALE_VEC    (N_NODES * H1 / 8)                        // 400000 (8 elems/thread)
#define SCALE_BLOCKS ((SCALE_VEC + 255) / 256)                 // 1563

// ---------------- scratch (static __device__ arrays — no allocation) ----------------
__device__ __align__(128) int    d_deg[N_NODES];
__device__ __align__(128) int    d_rowptr[N_NODES + 1];
__device__ __align__(128) int    d_cursor[N_NODES];
__device__ __align__(128) int    d_col[N_EDGES];
__device__ __align__(128) float  d_dinv[N_NODES];
__device__ __align__(128) float  d_g1[(size_t)N_NODES * H1];    // fp32 raw x@W1
__device__ __align__(128) __half d_g1h[(size_t)N_NODES * H1];   // fp16 dinv*(x@W1)
__device__ __align__(128) __half d_g2h[(size_t)N_NODES * H2];   // fp16 dinv*(h1@W2)
__device__ __align__(128) float  d_pool[N_GRAPHS * H2];
// decoupled-lookback scan state
__device__ int          d_ticket;
__device__ volatile int d_flag[SCAN_BLOCKS];   // 0=invalid 1=aggregate 2=prefix
__device__ volatile int d_agg[SCAN_BLOCKS];
__device__ volatile int d_pref[SCAN_BLOCKS];

// ---------------- 1. zero accumulators + scan state ----------------
__global__ void k_zero() {
    int i = blockIdx.x * blockDim.x + threadIdx.x;
    if (i < N_NODES) d_deg[i] = 0;
    if (i < N_GRAPHS * H2) d_pool[i] = 0.f;
    if (i < SCAN_BLOCKS) d_flag[i] = 0;
    if (i == 0) d_ticket = 0;
}

// ---------------- 2. fused: raw GEMM (g1 = x @ W1) || degree histogram ----------------
__global__ void __launch_bounds__(256) k_gemm_deg(const float* __restrict__ x,
                                                  const float* __restrict__ W1,
                                                  const int* __restrict__ ei) {
    if (blockIdx.x >= GEMM_BLOCKS) {
        int i = (blockIdx.x - GEMM_BLOCKS) * 256 + threadIdx.x;
        if (i < E4) {
            int4 dd = ((const int4*)(ei + N_EDGES))[i];
            if ((unsigned)dd.x < N_NODES) atomicAdd(&d_deg[dd.x], 1);
            if ((unsigned)dd.y < N_NODES) atomicAdd(&d_deg[dd.y], 1);
            if ((unsigned)dd.z < N_NODES) atomicAdd(&d_deg[dd.z], 1);
            if ((unsigned)dd.w < N_NODES) atomicAdd(&d_deg[dd.w], 1);
        }
        return;
    }
    __shared__ float xs[GEMM_TM * 132];   // padded rows, conflict-free
    int tid = threadIdx.x;
    int n0 = blockIdx.x * GEMM_TM;
    for (int i = tid; i < GEMM_TM * (IN_DIM / 4); i += 256) {
        int r = i >> 5, c = i & 31;
        float4 v = make_float4(0.f, 0.f, 0.f, 0.f);
        if (n0 + r < N_NODES)
            v = ((const float4*)(x + (size_t)(n0 + r) * IN_DIM))[c];
        *((float4*)(xs + r * 132 + c * 4)) = v;
    }
    __syncthreads();
    int tx = tid & 7;     // 8 col groups of 4
    int ty = tid >> 3;    // 32 node groups of 2
    const float* xr0 = xs + (2 * ty) * 132;
    const float* xr1 = xs + (2 * ty + 1) * 132;
    float a00 = 0.f, a01 = 0.f, a02 = 0.f, a03 = 0.f;
    float a10 = 0.f, a11 = 0.f, a12 = 0.f, a13 = 0.f;
    const float4* Wv = (const float4*)(W1) + tx;
#pragma unroll 8
    for (int k = 0; k < IN_DIM; k++) {
        float4 w = __ldg(Wv + k * 8);
        float p0 = xr0[k], p1 = xr1[k];
        a00 = fmaf(p0, w.x, a00); a01 = fmaf(p0, w.y, a01);
        a02 = fmaf(p0, w.z, a02); a03 = fmaf(p0, w.w, a03);
        a10 = fmaf(p1, w.x, a10); a11 = fmaf(p1, w.y, a11);
        a12 = fmaf(p1, w.z, a12); a13 = fmaf(p1, w.w, a13);
    }
    int n = n0 + 2 * ty;
    if (n < N_NODES)
        *((float4*)(d_g1 + (size_t)n * H1 + 4 * tx)) = make_float4(a00, a01, a02, a03);
    if (n + 1 < N_NODES)
        *((float4*)(d_g1 + (size_t)(n + 1) * H1 + 4 * tx)) = make_float4(a10, a11, a12, a13);
}

// ---------------- 3. single-pass decoupled-lookback scan + rowptr/cursor/dinv ----------------
__global__ void __launch_bounds__(256) k_scan() {
    __shared__ int s_bid, s_total, s_run;
    __shared__ int wsum[8], woff[8];
    int t = threadIdx.x;
    if (t == 0) s_bid = atomicAdd(&d_ticket, 1);
    __syncthreads();
    int b = s_bid;
    int i = b * 256 + t;
    int v = (i < N_NODES) ? d_deg[i] : 0;
    int lane = t & 31, wid = t >> 5;
    int x = v;
#pragma unroll
    for (int off = 1; off < 32; off <<= 1) {
        int y = __shfl_up_sync(0xffffffffu, x, off);
        if (lane >= off) x += y;
    }
    if (lane == 31) wsum[wid] = x;
    __syncthreads();
    if (t == 0) {
        int r = 0;
#pragma unroll
        for (int j = 0; j < 8; j++) { woff[j] = r; r += wsum[j]; }
        s_total = r;
        d_agg[b] = r;
        __threadfence();
        if (b == 0) { d_pref[0] = r; __threadfence(); d_flag[0] = 2; s_run = 0; }
        else        { d_flag[b] = 1; }
    }
    __syncthreads();
    int total = s_total;
    if (b > 0 && wid == 0) {
        // warp-parallel lookback, window of 32 predecessors
        int run = 0;
        int p = b - 1;
        while (true) {
            int idx = p - lane;
            int f = 0, a = 0;
            if (idx >= 0) {
                do { f = d_flag[idx]; } while (f == 0);
                a = (f == 2) ? d_pref[idx] : d_agg[idx];
            }
            unsigned pm = __ballot_sync(0xffffffffu, idx >= 0 && f == 2);
            int stop = pm ? (__ffs(pm) - 1) : 31;
            int contrib = (idx >= 0 && lane <= stop) ? a : 0;
#pragma unroll
            for (int off = 16; off; off >>= 1)
                contrib += __shfl_xor_sync(0xffffffffu, contrib, off);
            run += contrib;
            if (pm) break;
            p -= 32;
        }
        if (lane == 0) {
            d_pref[b] = run + total;
            __threadfence();
            d_flag[b] = 2;
            s_run = run;
        }
    }
    __syncthreads();
    int excl = s_run + woff[wid] + (x - v);
    if (i < N_NODES) {
        d_rowptr[i] = excl;
        d_cursor[i] = excl;
        d_dinv[i] = rsqrtf((float)(v + 1));
        if (i == N_NODES - 1) d_rowptr[N_NODES] = excl + v;
    }
}

// ---------------- 4. fused: CSR fill || g1h = half(dinv * g1) ----------------
__global__ void __launch_bounds__(256) k_csr_scale(const int* __restrict__ ei) {
    if (blockIdx.x < EDGE_BLOCKS) {
        int i = blockIdx.x * 256 + threadIdx.x;
        if (i < E4) {
            int4 ss = ((const int4*)ei)[i];
            int4 dd = ((const int4*)(ei + N_EDGES))[i];
            if ((unsigned)dd.x < N_NODES && (unsigned)ss.x < N_NODES)
                d_col[atomicAdd(&d_cursor[dd.x], 1)] = ss.x;
            if ((unsigned)dd.y < N_NODES && (unsigned)ss.y < N_NODES)
                d_col[atomicAdd(&d_cursor[dd.y], 1)] = ss.y;
            if ((unsigned)dd.z < N_NODES && (unsigned)ss.z < N_NODES)
                d_col[atomicAdd(&d_cursor[dd.z], 1)] = ss.z;
            if ((unsigned)dd.w < N_NODES && (unsigned)ss.w < N_NODES)
                d_col[atomicAdd(&d_cursor[dd.w], 1)] = ss.w;
        }
    } else {
        int i = (blockIdx.x - EDGE_BLOCKS) * 256 + threadIdx.x;
        if (i < SCALE_VEC) {                 // 8 floats -> 8 halves per thread
            int node = i >> 2;               // 4 threads per 32-elem row
            float di = d_dinv[node];
            float4 v0 = ((const float4*)d_g1)[2 * i];
            float4 v1 = ((const float4*)d_g1)[2 * i + 1];
            __half2 h[4];
            h[0] = __floats2half2_rn(v0.x * di, v0.y * di);
            h[1] = __floats2half2_rn(v0.z * di, v0.w * di);
            h[2] = __floats2half2_rn(v1.x * di, v1.y * di);
            h[3] = __floats2half2_rn(v1.z * di, v1.w * di);
            ((uint4*)d_g1h)[i] = *(uint4*)h;
        }
    }
}

// ---------------- 5. layer-1 aggregate (fp16 gather) + ReLU + (h1 @ W2) fused ----------------
__global__ void __launch_bounds__(256) k_agg1(const float* __restrict__ b1,
                                              const float* __restrict__ W2) {
    __shared__ float W2s[H1 * H2];
    int tid = threadIdx.x;
    for (int i = tid; i < H1 * H2; i += 256) W2s[i] = W2[i];
    __syncthreads();
    int wid = tid >> 5, lane = tid & 31;
    int node = blockIdx.x * 8 + wid;
    if (node >= N_NODES) return;

    float acc0 = __half2float(d_g1h[(size_t)node * H1 + lane]);  // self-loop
    float acc1 = 0.f;
    int s = d_rowptr[node], e = d_rowptr[node + 1];
    int i = s;
    for (; i + 8 <= e; i += 8) {
        int c0 = d_col[i],     c1 = d_col[i + 1], c2 = d_col[i + 2], c3 = d_col[i + 3];
        int c4 = d_col[i + 4], c5 = d_col[i + 5], c6 = d_col[i + 6], c7 = d_col[i + 7];
        float v0 = __half2float(d_g1h[(size_t)c0 * H1 + lane]);
        float v1 = __half2float(d_g1h[(size_t)c1 * H1 + lane]);
        float v2 = __half2float(d_g1h[(size_t)c2 * H1 + lane]);
        float v3 = __half2float(d_g1h[(size_t)c3 * H1 + lane]);
        float v4 = __half2float(d_g1h[(size_t)c4 * H1 + lane]);
        float v5 = __half2float(d_g1h[(size_t)c5 * H1 + lane]);
        float v6 = __half2float(d_g1h[(size_t)c6 * H1 + lane]);
        float v7 = __half2float(d_g1h[(size_t)c7 * H1 + lane]);
        acc0 += (v0 + v1) + (v2 + v3);
        acc1 += (v4 + v5) + (v6 + v7);
    }
    for (; i < e; ++i) acc0 += __half2float(d_g1h[(size_t)d_col[i] * H1 + lane]);
    float acc = acc0 + acc1;

    float di = d_dinv[node];
    float h = fmaxf(di * acc + b1[lane], 0.f);    // h1[node][lane]

    float o = 0.f;
    int f = lane & 15;
#pragma unroll
    for (int c = 0; c < H1; c++) {
        float v = __shfl_sync(0xffffffffu, h, c);
        o = fmaf(v, W2s[c * H2 + f], o);
    }
    if (lane < H2) d_g2h[(size_t)node * H2 + lane] = __float2half_rn(di * o);
}

// ---------------- 6. layer-2 aggregate (fp16 gather) + ReLU + mean-pool fused ----------------
__global__ void __launch_bounds__(256) k_agg2(const float* __restrict__ b2,
                                              const int* __restrict__ batch) {
    int tid = threadIdx.x;
    int wid = tid >> 5, lane = tid & 31;
    int node = blockIdx.x * 8 + wid;
    if (node >= N_NODES) return;

    int half = lane >> 4, f = lane & 15;
    float acc = (half == 0) ? __half2float(d_g2h[(size_t)node * H2 + f]) : 0.f;
    int s = d_rowptr[node], e = d_rowptr[node + 1];
    int i = s + half;
    for (; i + 6 < e; i += 8) {
        float v0 = __half2float(d_g2h[(size_t)d_col[i]     * H2 + f]);
        float v1 = __half2float(d_g2h[(size_t)d_col[i + 2] * H2 + f]);
        float v2 = __half2float(d_g2h[(size_t)d_col[i + 4] * H2 + f]);
        float v3 = __half2float(d_g2h[(size_t)d_col[i + 6] * H2 + f]);
        acc += (v0 + v1) + (v2 + v3);
    }
    for (; i < e; i += 2) acc += __half2float(d_g2h[(size_t)d_col[i] * H2 + f]);
    acc += __shfl_xor_sync(0xffffffffu, acc, 16);

    float di = d_dinv[node];
    float h = fmaxf(di * acc + b2[f], 0.f);

    int g = batch[node];
    if ((unsigned)g < N_GRAPHS && half == 0)
        atomicAdd(&d_pool[g * H2 + f], h);
}

// ---------------- 7. output head ----------------
__global__ void k_out(const int* __restrict__ batch, const float* __restrict__ W3,
                      const float* __restrict__ b3, float* __restrict__ out) {
    int g = blockIdx.x * blockDim.x + threadIdx.x;
    if (g >= N_GRAPHS) return;
    int lo0 = 0, hi0 = N_NODES;
    while (lo0 < hi0) { int m = (lo0 + hi0) >> 1; if (batch[m] < g) lo0 = m + 1; else hi0 = m; }
    int lo1 = lo0, hi1 = N_NODES;
    while (lo1 < hi1) { int m = (lo1 + hi1) >> 1; if (batch[m] < g + 1) lo1 = m + 1; else hi1 = m; }
    float c = fmaxf((float)(lo1 - lo0), 1.f);
    float sm = 0.f;
#pragma unroll
    for (int j = 0; j < H2; j++) sm = fmaf(d_pool[g * H2 + j], W3[j], sm);
    out[g] = sm / c + b3[0];
}

// ---------------- launch ----------------
extern "C" void kernel_launch(void* const* d_in, const int* in_sizes, int n_in,
                              void* d_out, int out_size) {
    const float* x     = (const float*)d_in[0];
    const int*   ei    = (const int*)d_in[1];
    const int*   batch = (const int*)d_in[2];
    const float* W1    = (const float*)d_in[3];
    const float* b1    = (const float*)d_in[4];
    const float* W2    = (const float*)d_in[5];
    const float* b2    = (const float*)d_in[6];
    const float* W3    = (const float*)d_in[7];
    const float* b3    = (const float*)d_in[8];
    float* out = (float*)d_out;

    const int NB = (N_NODES + 7) / 8;

    k_zero<<<SCAN_BLOCKS, 256>>>();
    k_gemm_deg<<<GEMM_BLOCKS + EDGE_BLOCKS, 256>>>(x, W1, ei);
    k_scan<<<SCAN_BLOCKS, 256>>>();
    k_csr_scale<<<EDGE_BLOCKS + SCALE_BLOCKS, 256>>>(ei);
    k_agg1<<<NB, 256>>>(b1, W2);
    k_agg2<<<NB, 256>>>(b2, batch);
    k_out<<<(N_GRAPHS + 255) / 256, 256>>>(batch, W3, b3, out);
}